// round 3
// baseline (speedup 1.0000x reference)
#include <cuda_runtime.h>
#include <cuda_bf16.h>
#include <math.h>

// Problem constants
#define BT   16     // batch
#define CH   1024   // channels
#define HW   48     // height/width
#define SP   24     // spatial tile
#define SS   576    // spatial area
#define HD   72     // mlp hidden
#define BB   64     // chunk batches (4 tiles * 16)
#define BLK  512    // channel block size
#define KTAY 12     // Taylor terms for exp(2ab)
#define JJ   24     // 2 blocks * KTAY

// ---------------- scratch (__device__ globals; no runtime alloc) ----------------
__device__ float g_H [BB*HD*CH];     // relu(W1_in . X)      (b,o,c)
__device__ float g_H2[BB*HD*CH];     // relu(W1_out . Z)     (b,o,d)
__device__ float g_O [BB*SS*CH];     // W2_out . H2 + b      (b,s,c)   151MB
__device__ float g_xm[BB*CH];
__device__ float g_u [BB*CH];        // exp(-xm^2)
__device__ float g_t [BB*2*KTAY];    // moments sum_c u*xm^k per (b,blk)
__device__ float g_T [BB*HD*JJ];     // H . Omega
__device__ float g_R [BB*HD*JJ];     // M2 . T + wv*t
__device__ float g_M2[HD*HD];        // W1_out . W2_in
__device__ float g_wv[HD];           // W1_out . b2_in
__device__ float g_mw2[HD];          // colmean(W2_in)
__device__ float g_mb2;
__device__ float g_bnSum[SS];
__device__ float g_bnSqr[SS];
__device__ float g_a [SS];           // 0.25*rsig*gamma
__device__ float g_bsh[SS];          // 0.25*(beta - mu*rsig*gamma)

// ---------------- prep kernels ----------------
__global__ void kp1(const float* __restrict__ w1o, const float* __restrict__ w2i,
                    const float* __restrict__ b2i) {
    int o = blockIdx.x, o2 = threadIdx.x;
    float acc = 0.f;
    for (int s = 0; s < SS; s++) acc = fmaf(w1o[o*SS + s], w2i[s*HD + o2], acc);
    g_M2[o*HD + o2] = acc;
    if (o2 == 0) {
        float a2 = 0.f;
        for (int s = 0; s < SS; s++) a2 = fmaf(w1o[o*SS + s], b2i[s], a2);
        g_wv[o] = a2;
    }
}

__global__ void kp2(const float* __restrict__ w2i, const float* __restrict__ b2i) {
    int t = threadIdx.x;
    if (t < HD) {
        float a = 0.f;
        for (int s = 0; s < SS; s++) a += w2i[s*HD + t];
        g_mw2[t] = a * (1.f/SS);
    }
    if (t < SS) { g_bnSum[t] = 0.f; g_bnSqr[t] = 0.f; }
    if (t == SS) {
        float a = 0.f;
        for (int s = 0; s < SS; s++) a += b2i[s];
        g_mb2 = a * (1.f/SS);
    }
}

// ---------------- K1: H = relu(W_in1 . Xg + b_in1), gather fused ----------------
// M=72 (full), N tile = 128 cols, K chunks of 24 (= one sy row, contiguous sx runs).
__global__ __launch_bounds__(256) void k1_gemm_in(const float* __restrict__ x,
        const float* __restrict__ w1, const float* __restrict__ b1) {
    __shared__ float As[24][73];    // [sk][o]
    __shared__ float Bs[24][132];   // [sk][c]  (pitch 132 keeps float4 align + conflict-free)
    int tid = threadIdx.x, warp = tid >> 5, lane = tid & 31;
    int n0 = blockIdx.x << 7;
    int b = n0 >> 10, c0 = n0 & 1023;
    int chunk = b >> 4, bt = b & 15;
    int ty = (chunk >> 1) * SP, tx = (chunk & 1) * SP;
    const float* xb = x + (bt*CH + c0) * (HW*HW) + ty*HW + tx;

    float acc[9][4];
#pragma unroll
    for (int i = 0; i < 9; i++) { acc[i][0]=acc[i][1]=acc[i][2]=acc[i][3]=0.f; }
    int m0 = warp * 9;

    for (int sy = 0; sy < 24; ++sy) {
        int k0 = sy * 24;
        for (int idx = tid; idx < HD*24; idx += 256) {
            int o = idx / 24, sk = idx - o*24;
            As[sk][o] = w1[o*SS + k0 + sk];
        }
        const float* xr = xb + sy * HW;
        for (int idx = tid; idx < 24*128; idx += 256) {
            int cl = idx / 24, sk = idx - cl*24;
            Bs[sk][cl] = xr[cl*(HW*HW) + sk];
        }
        __syncthreads();
#pragma unroll
        for (int sk = 0; sk < 24; ++sk) {
            float4 bv = *(const float4*)&Bs[sk][lane << 2];
#pragma unroll
            for (int i = 0; i < 9; i++) {
                float a = As[sk][m0 + i];
                acc[i][0] = fmaf(a, bv.x, acc[i][0]);
                acc[i][1] = fmaf(a, bv.y, acc[i][1]);
                acc[i][2] = fmaf(a, bv.z, acc[i][2]);
                acc[i][3] = fmaf(a, bv.w, acc[i][3]);
            }
        }
        __syncthreads();
    }
#pragma unroll
    for (int i = 0; i < 9; i++) {
        int o = m0 + i;
        float bias = b1[o];
        float4 r;
        r.x = fmaxf(acc[i][0] + bias, 0.f);
        r.y = fmaxf(acc[i][1] + bias, 0.f);
        r.z = fmaxf(acc[i][2] + bias, 0.f);
        r.w = fmaxf(acc[i][3] + bias, 0.f);
        *(float4*)&g_H[(b*HD + o)*CH + c0 + (lane << 2)] = r;
    }
}

// ---------------- K2: xm = colmean(W2_in).H + mean(b2), u = exp(-xm^2) ----------------
__global__ void k2_xm() {
    int b = blockIdx.x;
    int c = blockIdx.y * 256 + threadIdx.x;
    float acc = g_mb2;
    const float* hp = &g_H[b*HD*CH + c];
#pragma unroll 8
    for (int o = 0; o < HD; o++) acc = fmaf(g_mw2[o], hp[o*CH], acc);
    g_xm[b*CH + c] = acc;
    g_u [b*CH + c] = expf(-acc*acc);
}

// ---------------- K3: moments t_k = sum_c u*xm^k per (b,blk) ----------------
__global__ void k3_mom() {
    int bb = blockIdx.x;            // 0..127 = b*2+blk
    int b = bb >> 1, blk = bb & 1;
    int tid = threadIdx.x;
    float p[KTAY];
#pragma unroll
    for (int k = 0; k < KTAY; k++) p[k] = 0.f;
    for (int cl = tid; cl < BLK; cl += 256) {
        int c = b*CH + blk*BLK + cl;
        float xm = g_xm[c], pw = g_u[c];
        p[0] += pw;
#pragma unroll
        for (int k = 1; k < KTAY; k++) { pw *= xm; p[k] += pw; }
    }
    __shared__ float red[256];
    for (int k = 0; k < KTAY; k++) {
        red[tid] = p[k]; __syncthreads();
        for (int s = 128; s > 0; s >>= 1) {
            if (tid < s) red[tid] += red[tid + s];
            __syncthreads();
        }
        if (tid == 0) g_t[bb*KTAY + k] = red[0];
        __syncthreads();
    }
}

// ---------------- K4: T[b,o,(blk,k)] = sum_{c in blk} H[b,o,c]*u_c*xm_c^k ----------------
__global__ __launch_bounds__(864) void k4_T() {
    int bb = blockIdx.x; int b = bb >> 1, blk = bb & 1;
    int tid = threadIdx.x;
    int o = tid / KTAY, k = tid - o*KTAY;
    __shared__ float Hs[HD][65];
    __shared__ float ws[KTAY][66];
    float acc = 0.f;
    for (int c0 = 0; c0 < BLK; c0 += 64) {
        if (tid < KTAY*64) {
            int kk = tid / 64, cc = tid - kk*64;
            int c = b*CH + blk*BLK + c0 + cc;
            float xm = g_xm[c], pw = g_u[c];
            for (int t = 0; t < kk; t++) pw *= xm;
            ws[kk][cc] = pw;
        }
        for (int idx = tid; idx < HD*64; idx += 864) {
            int o2 = idx >> 6, cc = idx & 63;
            Hs[o2][cc] = g_H[(b*HD + o2)*CH + blk*BLK + c0 + cc];
        }
        __syncthreads();
#pragma unroll
        for (int cc = 0; cc < 64; cc++) acc = fmaf(Hs[o][cc], ws[k][cc], acc);
        __syncthreads();
    }
    g_T[(b*HD + o)*JJ + blk*KTAY + k] = acc;
}

// ---------------- K5: R = M2.T + wv (x) t ----------------
__global__ __launch_bounds__(864) void k5_R() {
    int b = blockIdx.x, tid = threadIdx.x;
    __shared__ float Ts[HD*JJ];
    for (int idx = tid; idx < HD*JJ; idx += 864) Ts[idx] = g_T[b*HD*JJ + idx];
    __syncthreads();
    int o = tid / KTAY, k = tid - o*KTAY;
    for (int half = 0; half < 2; ++half) {
        int jj = half*KTAY + k;
        float acc = g_wv[o] * g_t[b*JJ + jj];
#pragma unroll 8
        for (int o2 = 0; o2 < HD; o2++)
            acc = fmaf(g_M2[o*HD + o2], Ts[o2*JJ + jj], acc);
        g_R[b*HD*JJ + o*JJ + jj] = acc;
    }
}

// ---------------- K6: H2[b,o,d] = relu( (sum_k R*c_k*xm_d^k)/denom + b_out1 ) ----------------
__global__ __launch_bounds__(128) void k6_H2(const float* __restrict__ b1o) {
    int b = blockIdx.y;
    int d = blockIdx.x * 128 + threadIdx.x;
    int blk = d >> 9;
    __shared__ float Rs[HD*JJ];
    __shared__ float tb[JJ];
    __shared__ float bo[HD];
    for (int idx = threadIdx.x; idx < HD*JJ; idx += 128) Rs[idx] = g_R[b*HD*JJ + idx];
    if (threadIdx.x < JJ) tb[threadIdx.x] = g_t[b*JJ + threadIdx.x];
    if (threadIdx.x < HD) bo[threadIdx.x] = b1o[threadIdx.x];
    __syncthreads();
    float xm = g_xm[b*CH + d];
    float p[KTAY];
    p[0] = 1.f;
#pragma unroll
    for (int k = 1; k < KTAY; k++) p[k] = p[k-1] * (2.f * xm / (float)k);   // c_k * xm^k
    float denom = 0.f;
#pragma unroll
    for (int k = 0; k < KTAY; k++) denom = fmaf(p[k], tb[blk*KTAY + k], denom);
    float inv = 1.0f / denom;
    for (int o = 0; o < HD; o++) {
        float acc = 0.f;
#pragma unroll
        for (int k = 0; k < KTAY; k++) acc = fmaf(Rs[o*JJ + blk*KTAY + k], p[k], acc);
        g_H2[(b*HD + o)*CH + d] = fmaxf(fmaf(acc, inv, bo[o]), 0.f);
    }
}

// ---------------- K7: O = W_out2 . H2 + b_out2, with BN partial sums ----------------
// M=576 (tiles of 96), N tiles of 128, K=72 (chunks of 24).
__global__ __launch_bounds__(256) void k7_gemm_out(const float* __restrict__ w2o,
                                                   const float* __restrict__ b2o) {
    __shared__ float As[24][97];    // [k][m]
    __shared__ float Bs[24][132];   // [k][c]
    int tid = threadIdx.x, warp = tid >> 5, lane = tid & 31;
    int n0 = blockIdx.x << 7; int b = n0 >> 10, c0 = n0 & 1023;
    int mbase = blockIdx.y * 96;
    float acc[12][4];
#pragma unroll
    for (int i = 0; i < 12; i++) { acc[i][0]=acc[i][1]=acc[i][2]=acc[i][3]=0.f; }
    int m0 = warp * 12;

    for (int k0 = 0; k0 < HD; k0 += 24) {
        for (int idx = tid; idx < 96*24; idx += 256) {
            int m = idx / 24, kk = idx - m*24;
            As[kk][m] = w2o[(mbase + m)*HD + k0 + kk];
        }
        for (int idx = tid; idx < 24*128; idx += 256) {
            int kk = idx >> 7, cl = idx & 127;
            Bs[kk][cl] = g_H2[(b*HD + k0 + kk)*CH + c0 + cl];
        }
        __syncthreads();
#pragma unroll
        for (int kk = 0; kk < 24; kk++) {
            float4 bv = *(const float4*)&Bs[kk][lane << 2];
#pragma unroll
            for (int i = 0; i < 12; i++) {
                float a = As[kk][m0 + i];
                acc[i][0] = fmaf(a, bv.x, acc[i][0]);
                acc[i][1] = fmaf(a, bv.y, acc[i][1]);
                acc[i][2] = fmaf(a, bv.z, acc[i][2]);
                acc[i][3] = fmaf(a, bv.w, acc[i][3]);
            }
        }
        __syncthreads();
    }
#pragma unroll
    for (int i = 0; i < 12; i++) {
        int s = mbase + m0 + i;
        float bias = b2o[s];
        float4 v;
        v.x = acc[i][0] + bias; v.y = acc[i][1] + bias;
        v.z = acc[i][2] + bias; v.w = acc[i][3] + bias;
        *(float4*)&g_O[(b*SS + s)*CH + c0 + (lane << 2)] = v;
        float sm = v.x + v.y + v.z + v.w;
        float sq = v.x*v.x + v.y*v.y + v.z*v.z + v.w*v.w;
#pragma unroll
        for (int off = 16; off; off >>= 1) {
            sm += __shfl_xor_sync(0xffffffffu, sm, off);
            sq += __shfl_xor_sync(0xffffffffu, sq, off);
        }
        if (lane == 0) {
            atomicAdd(&g_bnSum[s], sm);
            atomicAdd(&g_bnSqr[s], sq);
        }
    }
}

// ---------------- K8: BN stats -> per-s affine (folded with 0.25 scatter scale) ----------------
__global__ void k8_stats(const float* __restrict__ gamma, const float* __restrict__ beta) {
    int s = threadIdx.x;
    if (s >= SS) return;
    const float n = (float)(BB*CH);
    float mu  = g_bnSum[s] / n;
    float var = g_bnSqr[s] / n - mu*mu;
    float rs  = rsqrtf(var + 1e-5f);
    float a   = rs * gamma[s];
    g_a  [s] = 0.25f * a;
    g_bsh[s] = 0.25f * (beta[s] - mu * a);
}

// ---------------- K9: normalize + scatter-add + relu (smem transpose) ----------------
__global__ __launch_bounds__(256) void k9_final(const float* __restrict__ x,
                                                float* __restrict__ out) {
    int b = blockIdx.z, sy = blockIdx.y, ct = blockIdx.x;
    int tid = threadIdx.x;
    __shared__ float Ts[24][129];
    __shared__ float av[24], bv[24];
    int c0 = ct << 7;
    int sbase = sy * 24;
    for (int idx = tid; idx < 24*128; idx += 256) {
        int sl = idx >> 7, cl = idx & 127;
        Ts[sl][cl] = g_O[(b*SS + sbase + sl)*CH + c0 + cl];
    }
    if (tid < 24) { av[tid] = g_a[sbase + tid]; bv[tid] = g_bsh[sbase + tid]; }
    __syncthreads();
    int chunk = b >> 4, bt = b & 15;
    int ty = (chunk >> 1) * SP, tx = (chunk & 1) * SP;
    for (int idx = tid; idx < 24*128; idx += 256) {
        int sx = idx % 24, cl = idx / 24;
        int c = c0 + cl;
        int addr = ((bt*CH + c)*HW + ty + sy)*HW + tx + sx;
        float val = fmaf(Ts[sx][cl], av[sx], bv[sx]);
        out[addr] = fmaxf(x[addr] + val, 0.f);
    }
}

// ---------------- launch ----------------
extern "C" void kernel_launch(void* const* d_in, const int* in_sizes, int n_in,
                              void* d_out, int out_size) {
    (void)in_sizes; (void)n_in; (void)out_size;
    const float* x      = (const float*)d_in[0];
    const float* w_in1  = (const float*)d_in[1];
    const float* b_in1  = (const float*)d_in[2];
    const float* w_in2  = (const float*)d_in[3];
    const float* b_in2  = (const float*)d_in[4];
    const float* w_out1 = (const float*)d_in[5];
    const float* b_out1 = (const float*)d_in[6];
    const float* w_out2 = (const float*)d_in[7];
    const float* b_out2 = (const float*)d_in[8];
    const float* gamma  = (const float*)d_in[9];
    const float* beta   = (const float*)d_in[10];
    float* out = (float*)d_out;

    kp1<<<HD, HD>>>(w_out1, w_in2, b_in2);
    kp2<<<1, 640>>>(w_in2, b_in2);
    k1_gemm_in<<<(BB*CH)/128, 256>>>(x, w_in1, b_in1);
    k2_xm<<<dim3(BB, CH/256), 256>>>();
    k3_mom<<<BB*2, 256>>>();
    k4_T<<<BB*2, 864>>>();
    k5_R<<<BB, 864>>>();
    k6_H2<<<dim3(CH/128, BB), 128>>>(b_out1);
    k7_gemm_out<<<dim3((BB*CH)/128, SS/96), 256>>>(w_out2, b_out2);
    k8_stats<<<1, SS>>>(gamma, beta);
    k9_final<<<dim3(CH/128, 24, BB), 256>>>(x, out);
}

// round 4
// speedup vs baseline: 1.0051x; 1.0051x over previous
#include <cuda_runtime.h>
#include <cuda_bf16.h>
#include <mma.h>
#include <math.h>

using namespace nvcuda;

// Problem constants
#define BT   16     // batch
#define CH   1024   // channels
#define HW   48     // height/width
#define SP   24     // spatial tile
#define SS   576    // spatial area
#define HD   72     // mlp hidden
#define BB   64     // chunk batches (4 tiles * 16)
#define BLK  512    // channel block size
#define KTAY 12     // Taylor terms for exp(2ab)
#define JJ   24     // 2 blocks * KTAY

// ---------------- scratch (__device__ globals; no runtime alloc) ----------------
__device__ float g_H [BB*HD*CH];     // relu(W1_in . X)      (b,o,c)
__device__ float g_H2[BB*HD*CH];     // relu(W1_out . Z)     (b,o,d)
__device__ float g_xm[BB*CH];
__device__ float g_u [BB*CH];        // exp(-xm^2)
__device__ float g_t [BB*JJ];        // moments sum_c u*xm^k per (b,blk)
__device__ float g_T [BB*HD*JJ];     // H . Omega
__device__ float g_R [BB*HD*JJ];     // M2 . T + wv*t
__device__ float g_M2[HD*HD];        // W1_out . W2_in
__device__ float g_wv[HD];           // W1_out . b2_in
__device__ float g_mw2[HD];          // colmean(W2_in)
__device__ float g_mb2;
__device__ float g_G [HD*HD];        // Gram of H2 (sum over b,c of h h^T)
__device__ float g_hs[HD];           // sum of H2
__device__ float g_a [SS];           // 0.25*rsig*gamma
__device__ float g_bsh[SS];          // 0.25*(beta + a*(bias - mu))

// ---------------- prep kernels ----------------
__global__ void kp1(const float* __restrict__ w1o, const float* __restrict__ w2i,
                    const float* __restrict__ b2i) {
    int o = blockIdx.x, o2 = threadIdx.x;
    float acc = 0.f;
    for (int s = 0; s < SS; s++) acc = fmaf(w1o[o*SS + s], w2i[s*HD + o2], acc);
    g_M2[o*HD + o2] = acc;
    if (o2 == 0) {
        float a2 = 0.f;
        for (int s = 0; s < SS; s++) a2 = fmaf(w1o[o*SS + s], b2i[s], a2);
        g_wv[o] = a2;
    }
}

__global__ void kp2(const float* __restrict__ w2i, const float* __restrict__ b2i) {
    int t = threadIdx.x;
    if (t < HD) {
        float a = 0.f;
        for (int s = 0; s < SS; s++) a += w2i[s*HD + t];
        g_mw2[t] = a * (1.f/SS);
    }
    for (int i = t; i < HD*HD; i += 640) g_G[i] = 0.f;
    if (t < HD) g_hs[t] = 0.f;
    if (t == 600) {
        float a = 0.f;
        for (int s = 0; s < SS; s++) a += b2i[s];
        g_mb2 = a * (1.f/SS);
    }
}

// ---------------- K1: H = relu(W_in1 . Xg + b_in1) via tf32 wmma; fused xm ----------------
// Block: M=80(pad of 72) x N=128 channels, K=576 in 12 chunks of 48 (=2 sy rows).
// 8 warps; warp w owns n16 column w, all 5 m16 rows.
__global__ __launch_bounds__(256) void k1_mma(const float* __restrict__ x,
        const float* __restrict__ w1, const float* __restrict__ b1) {
    __shared__ __align__(16) float smbuf[80*136];   // 43520 B
    float* As = smbuf;                // [80][52]
    float* Bs = smbuf + 80*52;        // [128][52]  (As+Bs = 10816 floats)
    float* Cs = smbuf;                // [80][136]  (aliases, used after loop)
    int tid = threadIdx.x, w = tid >> 5;
    int n0 = blockIdx.x << 7;
    int b = n0 >> 10, c0 = n0 & 1023;
    int chunk = b >> 4, bt = b & 15;
    int ty = (chunk >> 1) * SP, tx = (chunk & 1) * SP;
    const float* xb = x + (size_t)(bt*CH + c0) * 2304 + ty*48 + tx;

    wmma::fragment<wmma::accumulator,16,16,8,float> acc[5];
#pragma unroll
    for (int i = 0; i < 5; i++) wmma::fill_fragment(acc[i], 0.f);

    for (int kc = 0; kc < 12; ++kc) {
        int k0 = kc * 48;
        // stage A: w1 rows, zero-pad o>=72
        for (int idx = tid; idx < 80*48; idx += 256) {
            int o = idx / 48, kk = idx - o*48;
            As[o*52 + kk] = (o < HD) ? w1[o*SS + k0 + kk] : 0.f;
        }
        // stage B as [c][s] (natural, no transpose conflicts), float4 loads
        int sy0 = kc * 2;
        for (int q = tid; q < 128*12; q += 256) {
            int c = q / 12, qs = q - c*12;
            int row = (qs >= 6) ? 1 : 0;
            int sxx = (qs - row*6) * 4;
            float4 v = *(const float4*)(xb + (size_t)c*2304 + (sy0+row)*48 + sxx);
            *(float4*)&Bs[c*52 + row*24 + sxx] = v;
        }
        __syncthreads();
#pragma unroll
        for (int k8 = 0; k8 < 6; ++k8) {
            wmma::fragment<wmma::matrix_b,16,16,8,wmma::precision::tf32,wmma::col_major> bf;
            wmma::load_matrix_sync(bf, Bs + (w*16)*52 + k8*8, 52);
#pragma unroll
            for (int e = 0; e < bf.num_elements; e++) bf.x[e] = wmma::__float_to_tf32(bf.x[e]);
#pragma unroll
            for (int i = 0; i < 5; ++i) {
                wmma::fragment<wmma::matrix_a,16,16,8,wmma::precision::tf32,wmma::row_major> af;
                wmma::load_matrix_sync(af, As + (i*16)*52 + k8*8, 52);
#pragma unroll
                for (int e = 0; e < af.num_elements; e++) af.x[e] = wmma::__float_to_tf32(af.x[e]);
                wmma::mma_sync(acc[i], af, bf, acc[i]);
            }
        }
        __syncthreads();
    }
    // epilogue: frags -> Cs
#pragma unroll
    for (int i = 0; i < 5; ++i)
        wmma::store_matrix_sync(Cs + (i*16)*136 + w*16, acc[i], 136, wmma::mem_row_major);
    __syncthreads();
    // bias + relu + write H
    for (int idx = tid; idx < 72*32; idx += 256) {
        int o = idx >> 5, cq = (idx & 31) << 2;
        float bias = __ldg(&b1[o]);
        float4 v = *(float4*)&Cs[o*136 + cq];
        v.x = fmaxf(v.x + bias, 0.f); v.y = fmaxf(v.y + bias, 0.f);
        v.z = fmaxf(v.z + bias, 0.f); v.w = fmaxf(v.w + bias, 0.f);
        *(float4*)&g_H[(size_t)(b*HD + o)*CH + c0 + cq] = v;
    }
    // fused xm/u: full o-range lives in Cs
    if (tid < 128) {
        int c = tid;
        float a = g_mb2;
#pragma unroll 8
        for (int o = 0; o < HD; o++) {
            float h = fmaxf(Cs[o*136 + c] + __ldg(&b1[o]), 0.f);
            a = fmaf(g_mw2[o], h, a);
        }
        g_xm[b*CH + c0 + c] = a;
        g_u [b*CH + c0 + c] = expf(-a*a);
    }
}

// ---------------- K3: moments t_k = sum_c u*xm^k per (b,blk) ----------------
__global__ void k3_mom() {
    int bb = blockIdx.x;
    int b = bb >> 1, blk = bb & 1;
    int tid = threadIdx.x;
    float p[KTAY];
#pragma unroll
    for (int k = 0; k < KTAY; k++) p[k] = 0.f;
    for (int cl = tid; cl < BLK; cl += 256) {
        int c = b*CH + blk*BLK + cl;
        float xm = g_xm[c], pw = g_u[c];
        p[0] += pw;
#pragma unroll
        for (int k = 1; k < KTAY; k++) { pw *= xm; p[k] += pw; }
    }
    __shared__ float red[256];
    for (int k = 0; k < KTAY; k++) {
        red[tid] = p[k]; __syncthreads();
        for (int s = 128; s > 0; s >>= 1) {
            if (tid < s) red[tid] += red[tid + s];
            __syncthreads();
        }
        if (tid == 0) g_t[bb*KTAY + k] = red[0];
        __syncthreads();
    }
}

// ---------------- K4: T[b,o,(blk,k)] = sum_{c in blk} H[b,o,c]*u_c*xm_c^k ----------------
__global__ __launch_bounds__(864) void k4_T() {
    int bb = blockIdx.x; int b = bb >> 1, blk = bb & 1;
    int tid = threadIdx.x;
    int o = tid / KTAY, k = tid - o*KTAY;
    __shared__ float Hs[HD][65];
    __shared__ float ws[KTAY][66];
    float acc = 0.f;
    for (int c0 = 0; c0 < BLK; c0 += 64) {
        if (tid < KTAY*64) {
            int kk = tid / 64, cc = tid - kk*64;
            int c = b*CH + blk*BLK + c0 + cc;
            float xm = g_xm[c], pw = g_u[c];
            for (int t = 0; t < kk; t++) pw *= xm;
            ws[kk][cc] = pw;
        }
        for (int idx = tid; idx < HD*64; idx += 864) {
            int o2 = idx >> 6, cc = idx & 63;
            Hs[o2][cc] = g_H[(b*HD + o2)*CH + blk*BLK + c0 + cc];
        }
        __syncthreads();
#pragma unroll
        for (int cc = 0; cc < 64; cc++) acc = fmaf(Hs[o][cc], ws[k][cc], acc);
        __syncthreads();
    }
    g_T[(b*HD + o)*JJ + blk*KTAY + k] = acc;
}

// ---------------- K5: R = M2.T + wv (x) t ----------------
__global__ __launch_bounds__(864) void k5_R() {
    int b = blockIdx.x, tid = threadIdx.x;
    __shared__ float Ts[HD*JJ];
    for (int idx = tid; idx < HD*JJ; idx += 864) Ts[idx] = g_T[b*HD*JJ + idx];
    __syncthreads();
    int o = tid / KTAY, k = tid - o*KTAY;
    for (int half = 0; half < 2; ++half) {
        int jj = half*KTAY + k;
        float acc = g_wv[o] * g_t[b*JJ + jj];
#pragma unroll 8
        for (int o2 = 0; o2 < HD; o2++)
            acc = fmaf(g_M2[o*HD + o2], Ts[o2*JJ + jj], acc);
        g_R[b*HD*JJ + o*JJ + jj] = acc;
    }
}

// ---------------- K6: H2[b,o,d] = relu( (sum_k R*c_k*xm_d^k)/denom + b_out1 ) ----------------
__global__ __launch_bounds__(128) void k6_H2(const float* __restrict__ b1o) {
    int b = blockIdx.y;
    int d = blockIdx.x * 128 + threadIdx.x;
    int blk = d >> 9;
    __shared__ float Rs[HD*JJ];
    __shared__ float tb[JJ];
    __shared__ float bo[HD];
    for (int idx = threadIdx.x; idx < HD*JJ; idx += 128) Rs[idx] = g_R[b*HD*JJ + idx];
    if (threadIdx.x < JJ) tb[threadIdx.x] = g_t[b*JJ + threadIdx.x];
    if (threadIdx.x < HD) bo[threadIdx.x] = b1o[threadIdx.x];
    __syncthreads();
    float xm = g_xm[b*CH + d];
    float p[KTAY];
    p[0] = 1.f;
#pragma unroll
    for (int k = 1; k < KTAY; k++) p[k] = p[k-1] * (2.f * xm / (float)k);
    float denom = 0.f;
#pragma unroll
    for (int k = 0; k < KTAY; k++) denom = fmaf(p[k], tb[blk*KTAY + k], denom);
    float inv = 1.0f / denom;
    for (int o = 0; o < HD; o++) {
        float acc = 0.f;
#pragma unroll
        for (int k = 0; k < KTAY; k++) acc = fmaf(Rs[o*JJ + blk*KTAY + k], p[k], acc);
        g_H2[(b*HD + o)*CH + d] = fmaxf(fmaf(acc, inv, bo[o]), 0.f);
    }
}

// ---------------- K6g: Gram G = sum H2 H2^T, hsum = sum H2 ----------------
__global__ __launch_bounds__(288) void k6g() {
    int blk = blockIdx.x;                 // 128: (b, half of CH)
    int b = blk >> 1, c0 = (blk & 1) << 9;
    int tid = threadIdx.x;
    int i0 = (tid % 24) * 3, j0 = (tid / 24) * 6;
    __shared__ float Hs[HD][65];
    float acc[3][6];
#pragma unroll
    for (int i = 0; i < 3; i++)
#pragma unroll
        for (int j = 0; j < 6; j++) acc[i][j] = 0.f;
    float hs = 0.f;
    for (int cc0 = 0; cc0 < 512; cc0 += 64) {
        for (int idx = tid; idx < HD*64; idx += 288) {
            int o = idx >> 6, cc = idx & 63;
            Hs[o][cc] = g_H2[(size_t)(b*HD + o)*CH + c0 + cc0 + cc];
        }
        __syncthreads();
        if (tid < HD) {
#pragma unroll 16
            for (int cc = 0; cc < 64; cc++) hs += Hs[tid][cc];
        }
#pragma unroll 4
        for (int cc = 0; cc < 64; cc++) {
            float a0 = Hs[i0][cc], a1 = Hs[i0+1][cc], a2 = Hs[i0+2][cc];
#pragma unroll
            for (int jj = 0; jj < 6; ++jj) {
                float bv = Hs[j0+jj][cc];
                acc[0][jj] = fmaf(a0, bv, acc[0][jj]);
                acc[1][jj] = fmaf(a1, bv, acc[1][jj]);
                acc[2][jj] = fmaf(a2, bv, acc[2][jj]);
            }
        }
        __syncthreads();
    }
#pragma unroll
    for (int ii = 0; ii < 3; ii++)
#pragma unroll
        for (int jj = 0; jj < 6; jj++)
            atomicAdd(&g_G[(i0+ii)*HD + j0+jj], acc[ii][jj]);
    if (tid < HD) atomicAdd(&g_hs[tid], hs);
}

// ---------------- K8b: analytic BN stats per s -> folded affine ----------------
__global__ __launch_bounds__(128) void k8b(const float* __restrict__ w2o,
        const float* __restrict__ b2o, const float* __restrict__ gamma,
        const float* __restrict__ beta) {
    int s = blockIdx.x, t = threadIdx.x;
    __shared__ float rq[128], rd[128];
    float q = 0.f, d = 0.f;
    if (t < HD) {
        float wt = w2o[s*HD + t];
        float v = 0.f;
        for (int o2 = 0; o2 < HD; ++o2)
            v = fmaf(g_G[t*HD + o2], w2o[s*HD + o2], v);
        q = wt * v;
        d = wt * g_hs[t];
    }
    rq[t] = q; rd[t] = d;
    __syncthreads();
    for (int st = 64; st > 0; st >>= 1) {
        if (t < st) { rq[t] += rq[t+st]; rd[t] += rd[t+st]; }
        __syncthreads();
    }
    if (t == 0) {
        const float N = (float)(BB*CH);
        float bias = b2o[s];
        float dot = rd[0];
        float mu = dot / N + bias;
        float esq = rq[0]/N + 2.f*bias*dot/N + bias*bias;
        float var = esq - mu*mu;
        float a = rsqrtf(var + 1e-5f) * gamma[s];
        g_a  [s] = 0.25f * a;
        g_bsh[s] = 0.25f * (beta[s] + a*(bias - mu));
    }
}

// ---------------- K7f: O = W2o.H2 (tf32 wmma) fused with BN + scatter + relu ----------------
// Block: full M=576 x N=64 channels for one b. 12 warps; warp w owns m16 rows {w,w+12,w+24}.
// Epilogue in 6 passes of 96 s-rows, staged col-major in smem for transposed writes.
__global__ __launch_bounds__(384) void k7f(const float* __restrict__ w2o,
        const float* __restrict__ x, float* __restrict__ out) {
    __shared__ __align__(16) float Bs[HD*68];    // [o][c] pitch 68
    __shared__ __align__(16) float Os[64*96];    // [c][sl] pitch 96
    int tid = threadIdx.x, w = tid >> 5;
    int n0 = blockIdx.x << 6;
    int b = n0 >> 10, c0 = n0 & 1023;

    for (int idx = tid; idx < HD*64; idx += 384) {
        int o = idx >> 6, c = idx & 63;
        Bs[o*68 + c] = g_H2[(size_t)(b*HD + o)*CH + c0 + c];
    }
    __syncthreads();

    wmma::fragment<wmma::accumulator,16,16,8,float> acc[3][4];
#pragma unroll
    for (int j = 0; j < 3; j++)
#pragma unroll
        for (int cf = 0; cf < 4; cf++) wmma::fill_fragment(acc[j][cf], 0.f);

#pragma unroll
    for (int k8 = 0; k8 < 9; ++k8) {
        wmma::fragment<wmma::matrix_b,16,16,8,wmma::precision::tf32,wmma::row_major> bf[4];
#pragma unroll
        for (int cf = 0; cf < 4; cf++) {
            wmma::load_matrix_sync(bf[cf], Bs + (k8*8)*68 + cf*16, 68);
#pragma unroll
            for (int e = 0; e < bf[cf].num_elements; e++)
                bf[cf].x[e] = wmma::__float_to_tf32(bf[cf].x[e]);
        }
#pragma unroll
        for (int j = 0; j < 3; ++j) {
            wmma::fragment<wmma::matrix_a,16,16,8,wmma::precision::tf32,wmma::row_major> af;
            wmma::load_matrix_sync(af, w2o + (size_t)((w + 12*j)*16)*HD + k8*8, HD);
#pragma unroll
            for (int e = 0; e < af.num_elements; e++)
                af.x[e] = wmma::__float_to_tf32(af.x[e]);
#pragma unroll
            for (int cf = 0; cf < 4; cf++)
                wmma::mma_sync(acc[j][cf], af, bf[cf], acc[j][cf]);
        }
    }

    int chunk = b >> 4, bt = b & 15;
    int ty = (chunk >> 1)*SP, tx = (chunk & 1)*SP;
    const float* xb = x   + (size_t)(bt*CH + c0)*2304 + ty*48 + tx;
    float*       ob = out + (size_t)(bt*CH + c0)*2304 + ty*48 + tx;

    for (int p = 0; p < 6; ++p) {
        __syncthreads();
        if ((w < 6) == ((p & 1) == 0)) {
            int j  = p >> 1;
            int wl = w - 6*(p & 1);
#pragma unroll
            for (int cf = 0; cf < 4; ++cf)
                wmma::store_matrix_sync(Os + (cf*16)*96 + wl*16, acc[j][cf], 96,
                                        wmma::mem_col_major);
        }
        __syncthreads();
        int sy0 = p*4;
        for (int idx = tid; idx < 64*96; idx += 384) {
            int sx  = idx % 24;
            int t2  = idx / 24;
            int syl = t2 & 3;
            int c   = t2 >> 2;
            int sl  = syl*24 + sx;
            int s   = p*96 + sl;
            float v = Os[c*96 + sl];
            size_t ga = (size_t)c*2304 + (sy0+syl)*48 + sx;
            float r = fmaf(v, __ldg(&g_a[s]), __ldg(&g_bsh[s]));
            ob[ga] = fmaxf(xb[ga] + r, 0.f);
        }
    }
}

// ---------------- launch ----------------
extern "C" void kernel_launch(void* const* d_in, const int* in_sizes, int n_in,
                              void* d_out, int out_size) {
    (void)in_sizes; (void)n_in; (void)out_size;
    const float* x      = (const float*)d_in[0];
    const float* w_in1  = (const float*)d_in[1];
    const float* b_in1  = (const float*)d_in[2];
    const float* w_in2  = (const float*)d_in[3];
    const float* b_in2  = (const float*)d_in[4];
    const float* w_out1 = (const float*)d_in[5];
    const float* b_out1 = (const float*)d_in[6];
    const float* w_out2 = (const float*)d_in[7];
    const float* b_out2 = (const float*)d_in[8];
    const float* gamma  = (const float*)d_in[9];
    const float* beta   = (const float*)d_in[10];
    float* out = (float*)d_out;

    kp1<<<HD, HD>>>(w_out1, w_in2, b_in2);
    kp2<<<1, 640>>>(w_in2, b_in2);
    k1_mma<<<(BB*CH)/128, 256>>>(x, w_in1, b_in1);
    k3_mom<<<BB*2, 256>>>();
    k4_T<<<BB*2, 864>>>();
    k5_R<<<BB, 864>>>();
    k6_H2<<<dim3(CH/128, BB), 128>>>(b_out1);
    k6g<<<BB*2, 288>>>();
    k8b<<<SS, 128>>>(w_out2, b_out2, gamma, beta);
    k7f<<<(BB*CH)/64, 384>>>(w_out2, x, out);
}